// round 1
// baseline (speedup 1.0000x reference)
#include <cuda_runtime.h>
#include <cuda_fp16.h>
#include <mma.h>

using namespace nvcuda;

#define BATCH 8
#define QLEN  512
#define KLEN  4096
#define DIM   1024
#define HEADS 8
#define HD    128
#define SCALE 0.08838834764831845f   // 1/sqrt(128)

// ------------------------- scratch (device globals) -------------------------
__device__ __half g_h [BATCH * QLEN * DIM];            // ln(hidden)  8 MB
__device__ __half g_x [BATCH * KLEN * DIM];            // ln(inputs) 64 MB
__device__ __half g_wq[DIM * DIM];
__device__ __half g_wk[DIM * DIM];
__device__ __half g_wv[DIM * DIM];
__device__ __half g_q [BATCH * QLEN * DIM];            //  8 MB
__device__ __half g_k [BATCH * KLEN * DIM];            // 64 MB
__device__ __half g_v [BATCH * KLEN * DIM];            // 64 MB
__device__ float  g_s [(size_t)BATCH * HEADS * QLEN * KLEN]; // 512 MB scores
__device__ __half g_p [(size_t)BATCH * HEADS * QLEN * KLEN]; // 256 MB probs

// ------------------------- helpers -------------------------
__device__ __forceinline__ float blockReduce(float v, bool isMax, float* sbuf) {
    const unsigned FULL = 0xffffffffu;
    #pragma unroll
    for (int o = 16; o; o >>= 1) {
        float t = __shfl_xor_sync(FULL, v, o);
        v = isMax ? fmaxf(v, t) : (v + t);
    }
    int w = threadIdx.x >> 5, l = threadIdx.x & 31;
    if (l == 0) sbuf[w] = v;
    __syncthreads();
    float r = sbuf[0];
    #pragma unroll
    for (int i = 1; i < 8; i++) r = isMax ? fmaxf(r, sbuf[i]) : (r + sbuf[i]);
    __syncthreads();
    return r;
}

// ------------------------- cast fp32 -> fp16 (1M elements) -------------------------
__global__ void cast_kernel(const float* __restrict__ s, __half* __restrict__ d) {
    int i = blockIdx.x * 256 + threadIdx.x;          // one float4 per thread
    float4 v = ((const float4*)s)[i];
    ((__half2*)d)[i * 2]     = __floats2half2_rn(v.x, v.y);
    ((__half2*)d)[i * 2 + 1] = __floats2half2_rn(v.z, v.w);
}

// ------------------------- layernorm (1024 cols, 256 threads) -------------------------
__global__ void ln_kernel(const float* __restrict__ x, const float* __restrict__ w,
                          const float* __restrict__ b, __half* __restrict__ y) {
    size_t row = blockIdx.x;
    int t = threadIdx.x;
    __shared__ float sbuf[8];
    const float4* xr = (const float4*)(x + row * (size_t)DIM);
    float4 v = xr[t];
    float s = blockReduce(v.x + v.y + v.z + v.w, false, sbuf);
    float mean = s * (1.0f / DIM);
    float dx = v.x - mean, dy = v.y - mean, dz = v.z - mean, dw = v.w - mean;
    float sq = blockReduce(dx * dx + dy * dy + dz * dz + dw * dw, false, sbuf);
    float rstd = rsqrtf(sq * (1.0f / DIM) + 1e-5f);
    int c = t * 4;
    float o0 = dx * rstd * w[c]     + b[c];
    float o1 = dy * rstd * w[c + 1] + b[c + 1];
    float o2 = dz * rstd * w[c + 2] + b[c + 2];
    float o3 = dw * rstd * w[c + 3] + b[c + 3];
    __half2* yr = (__half2*)(y + row * (size_t)DIM);
    yr[t * 2]     = __floats2half2_rn(o0, o1);
    yr[t * 2 + 1] = __floats2half2_rn(o2, o3);
}

// ------------------------- row softmax: 4096 fp32 -> fp16 probs -------------------------
__global__ void softmax_kernel(const float* __restrict__ S, __half* __restrict__ P) {
    size_t row = blockIdx.x;
    int t = threadIdx.x;
    __shared__ float sbuf[8];
    const float4* sr = (const float4*)(S + row * (size_t)KLEN);
    float v[16];
    float mx = -1e30f;
    #pragma unroll
    for (int u = 0; u < 4; ++u) {
        float4 f = sr[t + u * 256];
        v[u * 4 + 0] = f.x; v[u * 4 + 1] = f.y; v[u * 4 + 2] = f.z; v[u * 4 + 3] = f.w;
        mx = fmaxf(mx, fmaxf(fmaxf(f.x, f.y), fmaxf(f.z, f.w)));
    }
    mx = blockReduce(mx, true, sbuf);
    float sum = 0.0f;
    #pragma unroll
    for (int i = 0; i < 16; ++i) { v[i] = __expf(v[i] - mx); sum += v[i]; }
    sum = blockReduce(sum, false, sbuf);
    float inv = 1.0f / sum;
    __half2* pr = (__half2*)(P + row * (size_t)KLEN);
    #pragma unroll
    for (int u = 0; u < 4; ++u) {
        int base = (t + u * 256) * 2;
        pr[base]     = __floats2half2_rn(v[u * 4 + 0] * inv, v[u * 4 + 1] * inv);
        pr[base + 1] = __floats2half2_rn(v[u * 4 + 2] * inv, v[u * 4 + 3] * inv);
    }
}

// ------------------------- generic wmma GEMM -------------------------
// C[M,N] = A[M,K] * op(B),  op(B)=B^T if BT (B is [N,K] row-major), else B is [K,N].
// Block tile 128x128x32, 8 warps (4x2), warp tile 32x64, wmma 16x16x16, fp32 accum.
// EPI 0: half out = acc + bias[n]   (aux = bias, no offsets)
// EPI 1: float out = acc * scale
// EPI 2: float out = acc + aux[same index]   (residual)
template<bool BT, int EPI>
__global__ void __launch_bounds__(256)
gemm_kernel(const __half* __restrict__ A, int lda, size_t aOffB, size_t aOffH,
            const __half* __restrict__ B, int ldb, size_t bOffB, size_t bOffH,
            void* __restrict__ Cv,        int ldc, size_t cOffB, size_t cOffH,
            const float* __restrict__ aux, size_t xOffB, size_t xOffH,
            float scale, int K)
{
    int z  = blockIdx.z;
    int bb = z / HEADS, hh = z % HEADS;
    A += bb * aOffB + hh * aOffH;
    B += bb * bOffB + hh * bOffH;
    size_t coff = (size_t)bb * cOffB + (size_t)hh * cOffH;
    const float* R = aux + (size_t)bb * xOffB + (size_t)hh * xOffH;

    int m0 = blockIdx.y * 128;
    int n0 = blockIdx.x * 128;

    __shared__ __align__(16) __half As[128 * 48];
    __shared__ __align__(16) __half Bs[128 * 48];     // also fits [32][144] = 4608
    __shared__ __align__(16) float  cpatch[8 * 16 * 20];

    int wid = threadIdx.x >> 5, lane = threadIdx.x & 31;
    int wm = wid & 3, wn = wid >> 2;

    wmma::fragment<wmma::accumulator, 16, 16, 16, float> acc[2][4];
    #pragma unroll
    for (int i = 0; i < 2; i++)
        #pragma unroll
        for (int j = 0; j < 4; j++)
            wmma::fill_fragment(acc[i][j], 0.0f);

    int KT = K >> 5;
    for (int kt = 0; kt < KT; ++kt) {
        int k0 = kt << 5;
        // load A tile [128 x 32]
        #pragma unroll
        for (int vv = 0; vv < 2; ++vv) {
            int li = threadIdx.x + vv * 256;
            int r = li >> 2, cvi = li & 3;
            *(int4*)&As[r * 48 + cvi * 8] =
                *(const int4*)&A[(size_t)(m0 + r) * lda + k0 + cvi * 8];
        }
        // load B tile
        if (BT) {   // [128 n x 32 k]
            #pragma unroll
            for (int vv = 0; vv < 2; ++vv) {
                int li = threadIdx.x + vv * 256;
                int r = li >> 2, cvi = li & 3;
                *(int4*)&Bs[r * 48 + cvi * 8] =
                    *(const int4*)&B[(size_t)(n0 + r) * ldb + k0 + cvi * 8];
            }
        } else {    // [32 k x 128 n], ld 144
            #pragma unroll
            for (int vv = 0; vv < 2; ++vv) {
                int li = threadIdx.x + vv * 256;
                int r = li >> 4, cvi = li & 15;
                *(int4*)&Bs[r * 144 + cvi * 8] =
                    *(const int4*)&B[(size_t)(k0 + r) * ldb + n0 + cvi * 8];
            }
        }
        __syncthreads();

        #pragma unroll
        for (int ks = 0; ks < 2; ++ks) {
            wmma::fragment<wmma::matrix_a, 16, 16, 16, __half, wmma::row_major> fa[2];
            #pragma unroll
            for (int i = 0; i < 2; i++)
                wmma::load_matrix_sync(fa[i], &As[(wm * 32 + i * 16) * 48 + ks * 16], 48);
            if (BT) {
                wmma::fragment<wmma::matrix_b, 16, 16, 16, __half, wmma::col_major> fb[4];
                #pragma unroll
                for (int j = 0; j < 4; j++)
                    wmma::load_matrix_sync(fb[j], &Bs[(wn * 64 + j * 16) * 48 + ks * 16], 48);
                #pragma unroll
                for (int i = 0; i < 2; i++)
                    #pragma unroll
                    for (int j = 0; j < 4; j++)
                        wmma::mma_sync(acc[i][j], fa[i], fb[j], acc[i][j]);
            } else {
                wmma::fragment<wmma::matrix_b, 16, 16, 16, __half, wmma::row_major> fb[4];
                #pragma unroll
                for (int j = 0; j < 4; j++)
                    wmma::load_matrix_sync(fb[j], &Bs[ks * 16 * 144 + wn * 64 + j * 16], 144);
                #pragma unroll
                for (int i = 0; i < 2; i++)
                    #pragma unroll
                    for (int j = 0; j < 4; j++)
                        wmma::mma_sync(acc[i][j], fa[i], fb[j], acc[i][j]);
            }
        }
        __syncthreads();
    }

    // epilogue via per-warp 16x16 smem patch
    float* patch = &cpatch[wid * 320];
    #pragma unroll
    for (int i = 0; i < 2; i++) {
        #pragma unroll
        for (int j = 0; j < 4; j++) {
            wmma::store_matrix_sync(patch, acc[i][j], 20, wmma::mem_row_major);
            __syncwarp();
            int m = m0 + wm * 32 + i * 16;
            int n = n0 + wn * 64 + j * 16;
            #pragma unroll
            for (int e = 0; e < 8; e++) {
                int idx = lane + e * 32;
                int r = idx >> 4, c = idx & 15;
                float val = patch[r * 20 + c];
                size_t off = coff + (size_t)(m + r) * ldc + (n + c);
                if constexpr (EPI == 0)
                    ((__half*)Cv)[off] = __float2half(val + R[n + c]);
                else if constexpr (EPI == 1)
                    ((float*)Cv)[off] = val * scale;
                else
                    ((float*)Cv)[off] = val + R[(size_t)(m + r) * ldc + (n + c)];
            }
            __syncwarp();
        }
    }
}

// ------------------------- launch -------------------------
extern "C" void kernel_launch(void* const* d_in, const int* in_sizes, int n_in,
                              void* d_out, int out_size) {
    const float* hid  = (const float*)d_in[0];
    const float* inp  = (const float*)d_in[1];
    const float* ln1w = (const float*)d_in[2];
    const float* ln1b = (const float*)d_in[3];
    const float* ln2w = (const float*)d_in[4];
    const float* ln2b = (const float*)d_in[5];
    const float* Wq   = (const float*)d_in[6];
    const float* bq   = (const float*)d_in[7];
    const float* Wk   = (const float*)d_in[8];
    const float* bk   = (const float*)d_in[9];
    const float* Wv   = (const float*)d_in[10];
    const float* bv   = (const float*)d_in[11];
    float* out = (float*)d_out;

    __half *p_h, *p_x, *p_wq, *p_wk, *p_wv, *p_q, *p_k, *p_v, *p_p;
    float* p_s;
    cudaGetSymbolAddress((void**)&p_h,  g_h);
    cudaGetSymbolAddress((void**)&p_x,  g_x);
    cudaGetSymbolAddress((void**)&p_wq, g_wq);
    cudaGetSymbolAddress((void**)&p_wk, g_wk);
    cudaGetSymbolAddress((void**)&p_wv, g_wv);
    cudaGetSymbolAddress((void**)&p_q,  g_q);
    cudaGetSymbolAddress((void**)&p_k,  g_k);
    cudaGetSymbolAddress((void**)&p_v,  g_v);
    cudaGetSymbolAddress((void**)&p_s,  g_s);
    cudaGetSymbolAddress((void**)&p_p,  g_p);

    // weight casts: 1024*1024 floats each, one float4/thread
    cast_kernel<<<1024, 256>>>(Wq, p_wq);
    cast_kernel<<<1024, 256>>>(Wk, p_wk);
    cast_kernel<<<1024, 256>>>(Wv, p_wv);

    // layernorms
    ln_kernel<<<BATCH * QLEN, 256>>>(hid, ln1w, ln1b, p_h);
    ln_kernel<<<BATCH * KLEN, 256>>>(inp, ln2w, ln2b, p_x);

    dim3 blk(256);
    // q = ln(h) @ Wq^T + bq   [4096 x 1024 x 1024]
    gemm_kernel<true, 0><<<dim3(8, 32, 1), blk>>>(
        p_h, DIM, 0, 0, p_wq, DIM, 0, 0, p_q, DIM, 0, 0, bq, 0, 0, 1.0f, DIM);
    // k = ln(x) @ Wk^T + bk   [32768 x 1024 x 1024]
    gemm_kernel<true, 0><<<dim3(8, 256, 1), blk>>>(
        p_x, DIM, 0, 0, p_wk, DIM, 0, 0, p_k, DIM, 0, 0, bk, 0, 0, 1.0f, DIM);
    // v = ln(x) @ Wv^T + bv
    gemm_kernel<true, 0><<<dim3(8, 256, 1), blk>>>(
        p_x, DIM, 0, 0, p_wv, DIM, 0, 0, p_v, DIM, 0, 0, bv, 0, 0, 1.0f, DIM);

    // scores: per (b,h)  S = q_h @ k_h^T * scale   [512 x 4096 x 128]
    gemm_kernel<true, 1><<<dim3(32, 4, BATCH * HEADS), blk>>>(
        p_q, DIM, (size_t)QLEN * DIM, HD,
        p_k, DIM, (size_t)KLEN * DIM, HD,
        p_s, KLEN, (size_t)HEADS * QLEN * KLEN, (size_t)QLEN * KLEN,
        nullptr, 0, 0, SCALE, HD);

    // softmax over 4096 keys, 32768 rows
    softmax_kernel<<<BATCH * HEADS * QLEN, 256>>>(p_s, p_p);

    // ctx + residual: per (b,h)  out = P @ V + hidden   [512 x 128 x 4096]
    gemm_kernel<false, 2><<<dim3(1, 4, BATCH * HEADS), blk>>>(
        p_p, KLEN, (size_t)HEADS * QLEN * KLEN, (size_t)QLEN * KLEN,
        p_v, DIM, (size_t)KLEN * DIM, HD,
        out, DIM, (size_t)QLEN * DIM, HD,
        hid, (size_t)QLEN * DIM, HD, 1.0f, KLEN);
}

// round 3
// speedup vs baseline: 1.6309x; 1.6309x over previous
#include <cuda_runtime.h>
#include <cuda_fp16.h>
#include <mma.h>
#include <cstdint>

using namespace nvcuda;

#define BATCH 8
#define QLEN  512
#define KLEN  4096
#define DIM   1024
#define HEADS 8
#define HD    128
#define SCALE 0.08838834764831845f   // 1/sqrt(128)

// ------------------------- scratch (device globals) -------------------------
__device__ __half g_h [BATCH * QLEN * DIM];            // ln(hidden)  8 MB
__device__ __half g_x [BATCH * KLEN * DIM];            // ln(inputs) 64 MB
__device__ __half g_wq[DIM * DIM];
__device__ __half g_wk[DIM * DIM];
__device__ __half g_wv[DIM * DIM];
__device__ __half g_q [BATCH * QLEN * DIM];            //  8 MB
__device__ __half g_k [BATCH * KLEN * DIM];            // 64 MB
__device__ __half g_v [BATCH * KLEN * DIM];            // 64 MB

// ------------------------- PTX helpers -------------------------
__device__ __forceinline__ uint32_t smem_u32(const void* p) {
    return (uint32_t)__cvta_generic_to_shared(p);
}
__device__ __forceinline__ void cp16(uint32_t dst, const void* src) {
    asm volatile("cp.async.cg.shared.global [%0], [%1], 16;\n" :: "r"(dst), "l"(src));
}
__device__ __forceinline__ void cp_commit() {
    asm volatile("cp.async.commit_group;\n");
}
__device__ __forceinline__ void ldm_x4(uint32_t addr, uint32_t& r0, uint32_t& r1,
                                       uint32_t& r2, uint32_t& r3) {
    asm volatile("ldmatrix.sync.aligned.m8n8.x4.shared.b16 {%0,%1,%2,%3}, [%4];\n"
                 : "=r"(r0), "=r"(r1), "=r"(r2), "=r"(r3) : "r"(addr));
}
__device__ __forceinline__ void ldm_x4_trans(uint32_t addr, uint32_t& r0, uint32_t& r1,
                                             uint32_t& r2, uint32_t& r3) {
    asm volatile("ldmatrix.sync.aligned.m8n8.x4.trans.shared.b16 {%0,%1,%2,%3}, [%4];\n"
                 : "=r"(r0), "=r"(r1), "=r"(r2), "=r"(r3) : "r"(addr));
}
__device__ __forceinline__ void mma16816(float* c, const uint32_t* a, uint32_t b0, uint32_t b1) {
    asm volatile("mma.sync.aligned.m16n8k16.row.col.f32.f16.f16.f32 "
                 "{%0,%1,%2,%3}, {%4,%5,%6,%7}, {%8,%9}, {%0,%1,%2,%3};\n"
                 : "+f"(c[0]), "+f"(c[1]), "+f"(c[2]), "+f"(c[3])
                 : "r"(a[0]), "r"(a[1]), "r"(a[2]), "r"(a[3]), "r"(b0), "r"(b1));
}
__device__ __forceinline__ uint32_t pack_h2(float a, float b) {
    __half2 h = __floats2half2_rn(a, b);
    return *reinterpret_cast<uint32_t*>(&h);
}

// ------------------------- cast fp32 -> fp16 (1M elements) -------------------------
__global__ void cast_kernel(const float* __restrict__ s, __half* __restrict__ d) {
    int i = blockIdx.x * 256 + threadIdx.x;
    float4 v = ((const float4*)s)[i];
    ((__half2*)d)[i * 2]     = __floats2half2_rn(v.x, v.y);
    ((__half2*)d)[i * 2 + 1] = __floats2half2_rn(v.z, v.w);
}

// ------------------------- layernorm: one warp per 1024-col row -------------------------
__global__ void ln_kernel(const float* __restrict__ x, const float* __restrict__ w,
                          const float* __restrict__ b, __half* __restrict__ y) {
    int row  = blockIdx.x * 8 + (threadIdx.x >> 5);
    int lane = threadIdx.x & 31;
    const float4* xr = (const float4*)(x + (size_t)row * DIM);
    float4 v[8];
    float s = 0.f;
    #pragma unroll
    for (int u = 0; u < 8; u++) {
        v[u] = xr[lane + u * 32];
        s += v[u].x + v[u].y + v[u].z + v[u].w;
    }
    #pragma unroll
    for (int o = 16; o; o >>= 1) s += __shfl_xor_sync(0xffffffffu, s, o);
    float mean = s * (1.f / DIM);
    float sq = 0.f;
    #pragma unroll
    for (int u = 0; u < 8; u++) {
        float a0 = v[u].x - mean, a1 = v[u].y - mean, a2 = v[u].z - mean, a3 = v[u].w - mean;
        sq += a0 * a0 + a1 * a1 + a2 * a2 + a3 * a3;
    }
    #pragma unroll
    for (int o = 16; o; o >>= 1) sq += __shfl_xor_sync(0xffffffffu, sq, o);
    float rstd = rsqrtf(sq * (1.f / DIM) + 1e-5f);
    __half2* yr = (__half2*)(y + (size_t)row * DIM);
    #pragma unroll
    for (int u = 0; u < 8; u++) {
        int c4 = lane + u * 32;
        float4 wv = ((const float4*)w)[c4];
        float4 bv = ((const float4*)b)[c4];
        float o0 = (v[u].x - mean) * rstd * wv.x + bv.x;
        float o1 = (v[u].y - mean) * rstd * wv.y + bv.y;
        float o2 = (v[u].z - mean) * rstd * wv.z + bv.z;
        float o3 = (v[u].w - mean) * rstd * wv.w + bv.w;
        yr[c4 * 2]     = __floats2half2_rn(o0, o1);
        yr[c4 * 2 + 1] = __floats2half2_rn(o2, o3);
    }
}

// ------------------------- projection GEMM: C = A @ B^T + bias (half out) ----------
// A [M,1024], B [N=1024 rows, 1024], block tile 128x128x32, cp.async 2-stage.
__global__ void __launch_bounds__(256)
gemm_bias_kernel(const __half* __restrict__ A, const __half* __restrict__ B,
                 __half* __restrict__ C, const float* __restrict__ bias)
{
    extern __shared__ __half sm[];
    const int m0 = blockIdx.y * 128;
    const int n0 = blockIdx.x * 128;
    const int tid = threadIdx.x;
    const int wid = tid >> 5, lane = tid & 31;
    const int wm = wid & 3, wn = wid >> 2;

    wmma::fragment<wmma::accumulator, 16, 16, 16, float> acc[2][4];
    #pragma unroll
    for (int i = 0; i < 2; i++)
        #pragma unroll
        for (int j = 0; j < 4; j++)
            wmma::fill_fragment(acc[i][j], 0.0f);

    auto issue = [&](int kt, int s) {
        const int k0 = kt * 32;
        __half* as = sm + s * 12288;
        __half* bs = as + 6144;
        #pragma unroll
        for (int i = 0; i < 2; i++) {
            int c = tid + i * 256;
            int r = c >> 2, col = (c & 3) * 8;
            cp16(smem_u32(&as[r * 48 + col]), &A[(size_t)(m0 + r) * DIM + k0 + col]);
            cp16(smem_u32(&bs[r * 48 + col]), &B[(size_t)(n0 + r) * DIM + k0 + col]);
        }
    };

    issue(0, 0); cp_commit();

    for (int kt = 0; kt < 32; kt++) {
        if (kt < 31) {
            issue(kt + 1, (kt + 1) & 1); cp_commit();
            asm volatile("cp.async.wait_group 1;\n");
        } else {
            asm volatile("cp.async.wait_group 0;\n");
        }
        __syncthreads();
        const __half* as = sm + (kt & 1) * 12288;
        const __half* bs = as + 6144;
        #pragma unroll
        for (int ks = 0; ks < 2; ks++) {
            wmma::fragment<wmma::matrix_a, 16, 16, 16, __half, wmma::row_major> fa[2];
            #pragma unroll
            for (int i = 0; i < 2; i++)
                wmma::load_matrix_sync(fa[i], &as[(wm * 32 + i * 16) * 48 + ks * 16], 48);
            wmma::fragment<wmma::matrix_b, 16, 16, 16, __half, wmma::col_major> fb[4];
            #pragma unroll
            for (int j = 0; j < 4; j++)
                wmma::load_matrix_sync(fb[j], &bs[(wn * 64 + j * 16) * 48 + ks * 16], 48);
            #pragma unroll
            for (int i = 0; i < 2; i++)
                #pragma unroll
                for (int j = 0; j < 4; j++)
                    wmma::mma_sync(acc[i][j], fa[i], fb[j], acc[i][j]);
        }
        __syncthreads();
    }

    // epilogue: reuse smem as per-warp fp32 patch
    float* patch = (float*)sm + wid * 320;
    #pragma unroll
    for (int i = 0; i < 2; i++) {
        #pragma unroll
        for (int j = 0; j < 4; j++) {
            wmma::store_matrix_sync(patch, acc[i][j], 20, wmma::mem_row_major);
            __syncwarp();
            int m = m0 + wm * 32 + i * 16;
            int n = n0 + wn * 64 + j * 16;
            #pragma unroll
            for (int e = 0; e < 8; e++) {
                int idx = lane + e * 32;
                int r = idx >> 4, c = idx & 15;
                C[(size_t)(m + r) * DIM + n + c] =
                    __float2half(patch[r * 20 + c] + bias[n + c]);
            }
            __syncwarp();
        }
    }
}

// ------------------------- fused flash attention + residual -------------------------
// grid (4 qtiles, 64 bh). 256 threads, warp w owns q-rows [16w,16w+16).
// smem: Qs[128][136] | Ks[2][128][136] | Vs[2][128][136]  (fp16, dynamic)
#define FROW 136
#define FTILE (128 * FROW)
#define FLASH_SMEM (5 * FTILE * 2)

__device__ __forceinline__ void flash_issue_kv(const __half* Kt, const __half* Vt,
                                               __half* kd, __half* vd, int tid) {
    #pragma unroll
    for (int i = 0; i < 8; i++) {
        int c = tid + i * 256;
        int r = c >> 4, col = (c & 15) * 8;
        cp16(smem_u32(&kd[r * FROW + col]), &Kt[(size_t)r * DIM + col]);
        cp16(smem_u32(&vd[r * FROW + col]), &Vt[(size_t)r * DIM + col]);
    }
}

__global__ void __launch_bounds__(256, 1)
flash_kernel(const __half* __restrict__ Qg, const __half* __restrict__ Kg,
             const __half* __restrict__ Vg, const float* __restrict__ hid,
             float* __restrict__ out)
{
    extern __shared__ __half sm[];
    __half* Qs = sm;
    __half* Ks = sm + FTILE;
    __half* Vs = sm + 3 * FTILE;

    const int bh = blockIdx.y;
    const int b = bh >> 3, h = bh & 7;
    const int q0 = blockIdx.x * 128;

    const __half* Qbase = Qg + (size_t)b * QLEN * DIM + h * HD;
    const __half* Kbase = Kg + (size_t)b * KLEN * DIM + h * HD;
    const __half* Vbase = Vg + (size_t)b * KLEN * DIM + h * HD;

    const int tid = threadIdx.x;
    const int w = tid >> 5, lane = tid & 31;

    // issue K0/V0 first so the loads overlap the Q staging
    flash_issue_kv(Kbase, Vbase, Ks, Vs, tid);
    cp_commit();

    // stage Q tile
    #pragma unroll
    for (int i = 0; i < 8; i++) {
        int c = tid + i * 256;
        int r = c >> 4, col = (c & 15) * 8;
        *(int4*)&Qs[r * FROW + col] = *(const int4*)&Qbase[(size_t)(q0 + r) * DIM + col];
    }
    __syncthreads();

    // Q fragments: qf[kk] covers q-rows [16w,16w+16) x d [16kk,16kk+16)
    uint32_t qf[8][4];
    {
        int r = w * 16 + ((lane >> 3) & 1) * 8 + (lane & 7);
        #pragma unroll
        for (int kk = 0; kk < 8; kk++) {
            int col = kk * 16 + (lane >> 4) * 8;
            ldm_x4(smem_u32(&Qs[r * FROW + col]), qf[kk][0], qf[kk][1], qf[kk][2], qf[kk][3]);
        }
    }

    float oacc[16][4];
    #pragma unroll
    for (int n = 0; n < 16; n++) { oacc[n][0] = 0; oacc[n][1] = 0; oacc[n][2] = 0; oacc[n][3] = 0; }
    float m0 = -1e30f, m1 = -1e30f, l0 = 0.f, l1 = 0.f;

    const int KT = KLEN / 128;   // 32
    for (int kt = 0; kt < KT; kt++) {
        const int buf = kt & 1;
        if (kt + 1 < KT) {
            flash_issue_kv(Kbase + (size_t)(kt + 1) * 128 * DIM,
                           Vbase + (size_t)(kt + 1) * 128 * DIM,
                           Ks + ((kt + 1) & 1) * FTILE, Vs + ((kt + 1) & 1) * FTILE, tid);
            cp_commit();
            asm volatile("cp.async.wait_group 1;\n");
        } else {
            asm volatile("cp.async.wait_group 0;\n");
        }
        __syncthreads();

        const __half* kb = Ks + buf * FTILE;
        const __half* vb = Vs + buf * FTILE;

        // ---- S = Q @ K^T  (16 rows x 128 keys per warp)
        float sacc[16][4];
        #pragma unroll
        for (int n = 0; n < 16; n++) { sacc[n][0] = 0; sacc[n][1] = 0; sacc[n][2] = 0; sacc[n][3] = 0; }
        #pragma unroll
        for (int kk = 0; kk < 8; kk++) {
            #pragma unroll
            for (int np = 0; np < 8; np++) {
                uint32_t b0, b1, b2, b3;
                int row = np * 16 + ((lane >> 4) << 3) + (lane & 7);
                int col = kk * 16 + ((lane >> 3) & 1) * 8;
                ldm_x4(smem_u32(&kb[row * FROW + col]), b0, b1, b2, b3);
                mma16816(sacc[2 * np],     qf[kk], b0, b1);
                mma16816(sacc[2 * np + 1], qf[kk], b2, b3);
            }
        }

        // ---- online softmax (rows: r0 = lane>>2, r1 = r0+8 of this warp's 16)
        float mx0 = -1e30f, mx1 = -1e30f;
        #pragma unroll
        for (int n = 0; n < 16; n++) {
            sacc[n][0] *= SCALE; sacc[n][1] *= SCALE; sacc[n][2] *= SCALE; sacc[n][3] *= SCALE;
            mx0 = fmaxf(mx0, fmaxf(sacc[n][0], sacc[n][1]));
            mx1 = fmaxf(mx1, fmaxf(sacc[n][2], sacc[n][3]));
        }
        mx0 = fmaxf(mx0, __shfl_xor_sync(0xffffffffu, mx0, 1));
        mx0 = fmaxf(mx0, __shfl_xor_sync(0xffffffffu, mx0, 2));
        mx1 = fmaxf(mx1, __shfl_xor_sync(0xffffffffu, mx1, 1));
        mx1 = fmaxf(mx1, __shfl_xor_sync(0xffffffffu, mx1, 2));
        float nm0 = fmaxf(m0, mx0), nm1 = fmaxf(m1, mx1);
        float sc0 = __expf(m0 - nm0), sc1 = __expf(m1 - nm1);
        m0 = nm0; m1 = nm1;
        l0 *= sc0; l1 *= sc1;
        #pragma unroll
        for (int n = 0; n < 16; n++) {
            oacc[n][0] *= sc0; oacc[n][1] *= sc0; oacc[n][2] *= sc1; oacc[n][3] *= sc1;
        }
        uint32_t pf[8][4];
        #pragma unroll
        for (int j = 0; j < 8; j++) {
            float p00 = __expf(sacc[2 * j][0] - m0),     p01 = __expf(sacc[2 * j][1] - m0);
            float p10 = __expf(sacc[2 * j][2] - m1),     p11 = __expf(sacc[2 * j][3] - m1);
            float p20 = __expf(sacc[2 * j + 1][0] - m0), p21 = __expf(sacc[2 * j + 1][1] - m0);
            float p30 = __expf(sacc[2 * j + 1][2] - m1), p31 = __expf(sacc[2 * j + 1][3] - m1);
            l0 += p00 + p01 + p20 + p21;
            l1 += p10 + p11 + p30 + p31;
            pf[j][0] = pack_h2(p00, p01);
            pf[j][1] = pack_h2(p10, p11);
            pf[j][2] = pack_h2(p20, p21);
            pf[j][3] = pack_h2(p30, p31);
        }

        // ---- O += P @ V
        #pragma unroll
        for (int j = 0; j < 8; j++) {
            #pragma unroll
            for (int np = 0; np < 8; np++) {
                uint32_t v0, v1, v2, v3;
                int row = j * 16 + ((lane >> 3) & 1) * 8 + (lane & 7);
                int col = np * 16 + (lane >> 4) * 8;
                ldm_x4_trans(smem_u32(&vb[row * FROW + col]), v0, v1, v2, v3);
                mma16816(oacc[2 * np],     pf[j], v0, v1);
                mma16816(oacc[2 * np + 1], pf[j], v2, v3);
            }
        }
        __syncthreads();
    }

    // ---- epilogue: O/l + residual
    l0 += __shfl_xor_sync(0xffffffffu, l0, 1);
    l0 += __shfl_xor_sync(0xffffffffu, l0, 2);
    l1 += __shfl_xor_sync(0xffffffffu, l1, 1);
    l1 += __shfl_xor_sync(0xffffffffu, l1, 2);
    float inv0 = 1.f / l0, inv1 = 1.f / l1;

    int r0 = q0 + w * 16 + (lane >> 2);
    int r1 = r0 + 8;
    size_t o0 = ((size_t)b * QLEN + r0) * DIM + h * HD;
    size_t o1 = ((size_t)b * QLEN + r1) * DIM + h * HD;
    #pragma unroll
    for (int n = 0; n < 16; n++) {
        int col = n * 8 + (lane & 3) * 2;
        float2 h0 = *(const float2*)&hid[o0 + col];
        float2 h1 = *(const float2*)&hid[o1 + col];
        float2 w0 = make_float2(oacc[n][0] * inv0 + h0.x, oacc[n][1] * inv0 + h0.y);
        float2 w1 = make_float2(oacc[n][2] * inv1 + h1.x, oacc[n][3] * inv1 + h1.y);
        *(float2*)&out[o0 + col] = w0;
        *(float2*)&out[o1 + col] = w1;
    }
}

// ------------------------- launch -------------------------
extern "C" void kernel_launch(void* const* d_in, const int* in_sizes, int n_in,
                              void* d_out, int out_size) {
    const float* hid  = (const float*)d_in[0];
    const float* inp  = (const float*)d_in[1];
    const float* ln1w = (const float*)d_in[2];
    const float* ln1b = (const float*)d_in[3];
    const float* ln2w = (const float*)d_in[4];
    const float* ln2b = (const float*)d_in[5];
    const float* Wq   = (const float*)d_in[6];
    const float* bq   = (const float*)d_in[7];
    const float* Wk   = (const float*)d_in[8];
    const float* bk   = (const float*)d_in[9];
    const float* Wv   = (const float*)d_in[10];
    const float* bv   = (const float*)d_in[11];
    float* out = (float*)d_out;

    __half *p_h, *p_x, *p_wq, *p_wk, *p_wv, *p_q, *p_k, *p_v;
    cudaGetSymbolAddress((void**)&p_h,  g_h);
    cudaGetSymbolAddress((void**)&p_x,  g_x);
    cudaGetSymbolAddress((void**)&p_wq, g_wq);
    cudaGetSymbolAddress((void**)&p_wk, g_wk);
    cudaGetSymbolAddress((void**)&p_wv, g_wv);
    cudaGetSymbolAddress((void**)&p_q,  g_q);
    cudaGetSymbolAddress((void**)&p_k,  g_k);
    cudaGetSymbolAddress((void**)&p_v,  g_v);

    cudaFuncSetAttribute(gemm_bias_kernel, cudaFuncAttributeMaxDynamicSharedMemorySize, 49152);
    cudaFuncSetAttribute(flash_kernel, cudaFuncAttributeMaxDynamicSharedMemorySize, FLASH_SMEM);

    cast_kernel<<<1024, 256>>>(Wq, p_wq);
    cast_kernel<<<1024, 256>>>(Wk, p_wk);
    cast_kernel<<<1024, 256>>>(Wv, p_wv);

    ln_kernel<<<BATCH * QLEN / 8, 256>>>(hid, ln1w, ln1b, p_h);
    ln_kernel<<<BATCH * KLEN / 8, 256>>>(inp, ln2w, ln2b, p_x);

    gemm_bias_kernel<<<dim3(8, 32),  256, 49152>>>(p_h, p_wq, p_q, bq);
    gemm_bias_kernel<<<dim3(8, 256), 256, 49152>>>(p_x, p_wk, p_k, bk);
    gemm_bias_kernel<<<dim3(8, 256), 256, 49152>>>(p_x, p_wv, p_v, bv);

    flash_kernel<<<dim3(4, 64), 256, FLASH_SMEM>>>(p_q, p_k, p_v, hid, out);
}